// round 10
// baseline (speedup 1.0000x reference)
#include <cuda_runtime.h>
#include <math.h>

#define H        128
#define WST      132      // weight matrix row stride (words); 132%32==4
#define VS       136      // vector sample stride
#define VIX(s,j) ((s)*VS + (j) + ((((j)>>6))<<2))   // pad 4 words at j=64
#define NCTA     128
#define NTHREADS 512
#define MAXIT    500
#define TOLF     1e-3f

// per-(iteration, CTA) residual slots; -1 = not posted, >=0 = posted value.
__device__ float g_part[MAXIT * NCTA];

struct __align__(16) Smem {
    float Wy0[H * WST];
    float Wy1[H * WST];
    float W1p[H * WST];
    float xbuf[2 * VS];
    float ubuf0[2 * VS];
    float ubuf1[2 * VS];
    float yv0[2 * VS];
    float yv1[2 * VS];
    float zz [2 * VS];
    float v2 [2 * VS];
    float v1 [2 * VS];
    float my1[2 * VS];
    float gAb[2 * VS];
    float cA[2 * VS], cB[2 * VS], cC[2 * VS], cD[2 * VS], cE[2 * VS], cF[2 * VS];
    float red[8][2];
    float zu2[2];
    int   flag;
};

__global__ void pblnn_init_kernel() {
    int t = blockIdx.x * blockDim.x + threadIdx.x;
    if (t < MAXIT * NCTA) g_part[t] = -1.f;
}

__device__ __forceinline__ float softplus_f(float s) {
    float e = __expf(s);
    float z = __logf(1.f + e);
    return (s > 15.f) ? s : z;
}

__device__ __forceinline__ void spsig(float s, float& z, float& sg) {
    float e = __expf(s);
    float zz_ = __logf(1.f + e);
    float sgg = e / (1.f + e);
    if (s > 15.f) { zz_ = s; sgg = 1.f; }
    z = zz_; sg = sgg;
}

// 64-wide dual-sample row dot, gmem weights (one-time precompute).
// Wrow points at W[h*128]; jo = 64*half; pad = 4*half.
__device__ __forceinline__ void pdotg(const float* __restrict__ Wrow, const float* vec,
                                      int jo, int pad, float& r0, float& r1) {
    float a0 = 0.f, b0 = 0.f, a1 = 0.f, b1 = 0.f;
#pragma unroll
    for (int t = 0; t < 16; t += 2) {
        float4 w  = __ldg((const float4*)&Wrow[jo + 4*t]);
        float4 w2 = __ldg((const float4*)&Wrow[jo + 4*t + 4]);
        float4 x0  = *(const float4*)&vec[jo + pad + 4*t];
        float4 x02 = *(const float4*)&vec[jo + pad + 4*t + 4];
        float4 x1  = *(const float4*)&vec[VS + jo + pad + 4*t];
        float4 x12 = *(const float4*)&vec[VS + jo + pad + 4*t + 4];
        a0 += w.x*x0.x + w.y*x0.y + w.z*x0.z + w.w*x0.w;
        b0 += w2.x*x02.x + w2.y*x02.y + w2.z*x02.z + w2.w*x02.w;
        a1 += w.x*x1.x + w.y*x1.y + w.z*x1.z + w.w*x1.w;
        b1 += w2.x*x12.x + w2.y*x12.y + w2.z*x12.z + w2.w*x12.w;
    }
    r0 = a0 + b0; r1 = a1 + b1;
}

// 64-wide dual-sample row dot, smem weights (stride WST).
__device__ __forceinline__ void sdot(const float* Wrow, const float* vec,
                                     int jo, int pad, float& r0, float& r1) {
    float a0 = 0.f, b0 = 0.f, a1 = 0.f, b1 = 0.f;
#pragma unroll
    for (int t = 0; t < 16; t += 2) {
        float4 w  = *(const float4*)&Wrow[jo + 4*t];
        float4 w2 = *(const float4*)&Wrow[jo + 4*t + 4];
        float4 x0  = *(const float4*)&vec[jo + pad + 4*t];
        float4 x02 = *(const float4*)&vec[jo + pad + 4*t + 4];
        float4 x1  = *(const float4*)&vec[VS + jo + pad + 4*t];
        float4 x12 = *(const float4*)&vec[VS + jo + pad + 4*t + 4];
        a0 += w.x*x0.x + w.y*x0.y + w.z*x0.z + w.w*x0.w;
        b0 += w2.x*x02.x + w2.y*x02.y + w2.z*x02.z + w2.w*x02.w;
        a1 += w.x*x1.x + w.y*x1.y + w.z*x1.z + w.w*x1.w;
        b1 += w2.x*x12.x + w2.y*x12.y + w2.z*x12.z + w2.w*x12.w;
    }
    r0 = a0 + b0; r1 = a1 + b1;
}

// 64-deep dual-sample column dot, smem weights; per-half stagger for banks.
__device__ __forceinline__ void cdot(const float* Wm, const float* vec,
                                     int h, int half, float& r0, float& r1) {
    float a0 = 0.f, a1 = 0.f;
    const int jo = half * 64, pad = half * 4;
#pragma unroll
    for (int t = 0; t < 16; t++) {
        int m = (4*t + 4*half) & 63;
        int j = jo + m;
        float4 x0 = *(const float4*)&vec[j + pad];
        float4 x1 = *(const float4*)&vec[VS + j + pad];
        const float* col = &Wm[j * WST + h];
        float w0 = col[0], w1 = col[WST], w2 = col[2*WST], w3 = col[3*WST];
        a0 += w0*x0.x + w1*x0.y + w2*x0.z + w3*x0.w;
        a1 += w0*x1.x + w1*x1.y + w2*x1.z + w3*x1.w;
    }
    r0 = a0; r1 = a1;
}

#define COMB2(r0, r1) { r0 += __shfl_xor_sync(0xffffffffu, r0, 16); \
                        r1 += __shfl_xor_sync(0xffffffffu, r1, 16); }

__global__ __launch_bounds__(NTHREADS, 1)
void pblnn_kernel(
    const float* __restrict__ x,      const float* __restrict__ y,
    const float* __restrict__ wuu0_w, const float* __restrict__ wuu0_b,
    const float* __restrict__ wyu0_w, const float* __restrict__ wyu0_b,
    const float* __restrict__ wy0,
    const float* __restrict__ wu0_w,  const float* __restrict__ wu0_b,
    const float* __restrict__ wuu1_w, const float* __restrict__ wuu1_b,
    const float* __restrict__ wzu1_w, const float* __restrict__ wzu1_b,
    const float* __restrict__ wz1,
    const float* __restrict__ wyu1_w, const float* __restrict__ wyu1_b,
    const float* __restrict__ wy1,
    const float* __restrict__ wu1_w,  const float* __restrict__ wu1_b,
    const float* __restrict__ wzu2_w, const float* __restrict__ wzu2_b,
    const float* __restrict__ wz2,
    const float* __restrict__ wyu2_w, const float* __restrict__ wyu2_b,
    const float* __restrict__ wy2,
    float* __restrict__ out)
{
    extern __shared__ char smem_raw[];
    Smem& S = *reinterpret_cast<Smem*>(smem_raw);

    const int tid  = threadIdx.x;
    const int l    = tid & 31;
    const int w    = tid >> 5;
    const int grp  = w >> 3;            // 0 = A warps, 1 = B warps
    const int wh   = w & 7;
    const int hb   = l & 15;
    const int half = l >> 4;
    const int h    = wh * 16 + hb;
    const bool lead = (l < 16);
    const int jo   = half * 64;
    const int pad  = half * 4;
    const int samp = blockIdx.x * 2;

    // ---- stage weights (fp32, stride WST) + x (VIX layout) ----
    for (int e = tid; e < H * H / 4; e += NTHREADS) {
        int r = e >> 5, c4 = (e & 31) * 4;
        *(float4*)&S.Wy0[r * WST + c4] = __ldg((const float4*)&wy0[r * H + c4]);
        *(float4*)&S.Wy1[r * WST + c4] = __ldg((const float4*)&wy1[r * H + c4]);
        float4 wv = __ldg((const float4*)&wz1[r * H + c4]);
        wv.x = fmaxf(wv.x, 0.f); wv.y = fmaxf(wv.y, 0.f);
        wv.z = fmaxf(wv.z, 0.f); wv.w = fmaxf(wv.w, 0.f);
        *(float4*)&S.W1p[r * WST + c4] = wv;
    }
    for (int e = tid; e < 2 * H; e += NTHREADS) {
        int s = e >> 7, j = e & 127;
        S.xbuf[VIX(s, j)] = x[samp * H + e];
    }
    __syncthreads();

    // ---- y-independent precompute: paired matvecs on A/B warp groups ----
    float p0, p1;
    // R1: A: u0 = sp(wuu0@x+b) ; B: a0 = wyu0@x+b
    pdotg(grp == 0 ? &wuu0_w[h * H] : &wyu0_w[h * H], S.xbuf, jo, pad, p0, p1);
    COMB2(p0, p1)
    if (lead) {
        if (grp == 0) {
            S.ubuf0[VIX(0, h)] = softplus_f(p0 + wuu0_b[h]);
            S.ubuf0[VIX(1, h)] = softplus_f(p1 + wuu0_b[h]);
        } else {
            S.cA[VIX(0, h)] = p0 + wyu0_b[h];
            S.cA[VIX(1, h)] = p1 + wyu0_b[h];
        }
    }
    __syncthreads();
    // R2: A: c0 = wu0@x+b ; B: u1 = sp(wuu1@u0+b)
    pdotg(grp == 0 ? &wu0_w[h * H] : &wuu1_w[h * H],
          grp == 0 ? S.xbuf : S.ubuf0, jo, pad, p0, p1);
    COMB2(p0, p1)
    if (lead) {
        if (grp == 0) {
            S.cB[VIX(0, h)] = p0 + wu0_b[h];
            S.cB[VIX(1, h)] = p1 + wu0_b[h];
        } else {
            S.ubuf1[VIX(0, h)] = softplus_f(p0 + wuu1_b[h]);
            S.ubuf1[VIX(1, h)] = softplus_f(p1 + wuu1_b[h]);
        }
    }
    __syncthreads();
    // R3: A: zur = sp(wzu1@u0+b) ; B: a1 = wyu1@u0+b
    pdotg(grp == 0 ? &wzu1_w[h * H] : &wyu1_w[h * H], S.ubuf0, jo, pad, p0, p1);
    COMB2(p0, p1)
    if (lead) {
        if (grp == 0) {
            S.cC[VIX(0, h)] = softplus_f(p0 + wzu1_b[h]);
            S.cC[VIX(1, h)] = softplus_f(p1 + wzu1_b[h]);
        } else {
            S.cD[VIX(0, h)] = p0 + wyu1_b[h];
            S.cD[VIX(1, h)] = p1 + wyu1_b[h];
        }
    }
    __syncthreads();
    // R4: A: c1 = wu1@u0+b ; B: a2t = wyu2@u1+b
    pdotg(grp == 0 ? &wu1_w[h * H] : &wyu2_w[h * H],
          grp == 0 ? S.ubuf0 : S.ubuf1, jo, pad, p0, p1);
    COMB2(p0, p1)
    if (lead) {
        if (grp == 0) {
            S.cE[VIX(0, h)] = p0 + wu1_b[h];
            S.cE[VIX(1, h)] = p1 + wu1_b[h];
        } else {
            S.cF[VIX(0, h)] = p0 + wyu2_b[h];
            S.cF[VIX(1, h)] = p1 + wyu2_b[h];
        }
    }
    __syncthreads();
    // zu2[s] = sp(wzu2 . u1[s] + b): warp 0, lane covers 4 h's
    if (w == 0) {
        float4 wv = __ldg((const float4*)&wzu2_w[4 * l]);
        float4 u0v = *(const float4*)&S.ubuf1[VIX(0, 4 * l)];
        float4 u1v = *(const float4*)&S.ubuf1[VIX(1, 4 * l)];
        float s0 = wv.x*u0v.x + wv.y*u0v.y + wv.z*u0v.z + wv.w*u0v.w;
        float s1 = wv.x*u1v.x + wv.y*u1v.y + wv.z*u1v.z + wv.w*u1v.w;
#pragma unroll
        for (int o = 16; o; o >>= 1) {
            s0 += __shfl_xor_sync(0xffffffffu, s0, o);
            s1 += __shfl_xor_sync(0xffffffffu, s1, o);
        }
        if (l == 0) {
            S.zu2[0] = softplus_f(s0 + wzu2_b[0]);
            S.zu2[1] = softplus_f(s1 + wzu2_b[0]);
        }
    }
    __syncthreads();

    // ---- gather per-(h,s) constants into A-lead registers ----
    float a0r[2], c0r[2], zur[2], a1r[2], c1r[2], a2w[2], vw2[2];
    float yr_[2], y1r_[2], yh_[2], zs1_[2];
    a0r[0]=a0r[1]=c0r[0]=c0r[1]=zur[0]=zur[1]=a1r[0]=a1r[1]=0.f;
    c1r[0]=c1r[1]=a2w[0]=a2w[1]=vw2[0]=vw2[1]=yr_[0]=yr_[1]=0.f;
    y1r_[0]=y1r_[1]=yh_[0]=yh_[1]=1.f; zs1_[0]=zs1_[1]=0.f;
    if (grp == 0 && lead) {
        float wy2h = wy2[h], w2p = fmaxf(wz2[h], 0.f);
#pragma unroll
        for (int s = 0; s < 2; s++) {
            a0r[s] = S.cA[VIX(s, h)];
            c0r[s] = S.cB[VIX(s, h)];
            zur[s] = S.cC[VIX(s, h)];
            a1r[s] = S.cD[VIX(s, h)];
            c1r[s] = S.cE[VIX(s, h)];
            a2w[s] = S.cF[VIX(s, h)] * wy2h;
            vw2[s] = S.zu2[s] * w2p;
            yr_[s] = y[(samp + s) * H + h];
            S.yv0[VIX(s, h)] = a0r[s];   // y1 = 1
            S.yv1[VIX(s, h)] = a1r[s];
        }
    }
    __syncthreads();   // yv ready for iter 0

    // ---- fixed-point iterations: 4 barriers/iter, lag-2 pipeline ----
    int broke = 0;
    for (int it = 0; it < MAXIT; ++it) {
        // P1: A: Wy0@yv0 ; B: Wy1@yv1 (independent)
        sdot(grp == 0 ? &S.Wy0[h * WST] : &S.Wy1[h * WST],
             grp == 0 ? S.yv0 : S.yv1, jo, pad, p0, p1);
        COMB2(p0, p1)
        if (lead) {
            if (grp == 0) {
                float z0, sg0, z1, sg1;
                spsig(p0 + c0r[0], z0, sg0);
                spsig(p1 + c0r[1], z1, sg1);
                zs1_[0] = sg0 * zur[0];  zs1_[1] = sg1 * zur[1];
                S.zz[VIX(0, h)] = z0 * zur[0];
                S.zz[VIX(1, h)] = z1 * zur[1];
            } else {
                S.my1[VIX(0, h)] = p0;
                S.my1[VIX(1, h)] = p1;
            }
        }
        __syncthreads();                                   // bar 1

        // P2: A: W1p@zz -> v2 ; B warps: poster (w8) + checker (w12)
        if (grp == 0) {
            sdot(&S.W1p[h * WST], S.zz, jo, pad, p0, p1);
            COMB2(p0, p1)
            if (lead) {
                float s2a = p0 + S.my1[VIX(0, h)] + c1r[0];
                float s2b = p1 + S.my1[VIX(1, h)] + c1r[1];
                S.v2[VIX(0, h)] = vw2[0] / (1.f + __expf(-s2a));
                S.v2[VIX(1, h)] = vw2[1] / (1.f + __expf(-s2b));
            }
        } else {
            if (w == 8 && l == 0 && it > 0) {
                float n0 = 0.f, n1 = 0.f;
#pragma unroll
                for (int i = 0; i < 8; i++) { n0 += S.red[i][0]; n1 += S.red[i][1]; }
                *((volatile float*)&g_part[(it - 1) * NCTA + blockIdx.x])
                    = sqrtf(n0) + sqrtf(n1);
            }
            if (w == 12) {
                int f = 0;
                if (it >= 2) {
                    volatile const float* gp = &g_part[(it - 2) * NCTA];
                    float sum;
                    for (;;) {
                        float v0 = gp[l], v1 = gp[l + 32];
                        float v2v = gp[l + 64], v3 = gp[l + 96];
                        bool ok = (v0 >= 0.f) & (v1 >= 0.f) & (v2v >= 0.f) & (v3 >= 0.f);
                        if (__all_sync(0xffffffffu, ok)) { sum = v0 + v1 + v2v + v3; break; }
                    }
#pragma unroll
                    for (int o = 16; o; o >>= 1)
                        sum += __shfl_xor_sync(0xffffffffu, sum, o);
                    if (sum * (1.f / 256.f) < TOLF) f = 1;
                }
                if (l == 0) S.flag = f;
            }
        }
        __syncthreads();                                   // bar 2

        // P3: A: tv = W1p^T @ v2 -> v1 ; B: gA = Wy1^T @ v2
        cdot(grp == 0 ? S.W1p : S.Wy1, S.v2, h, half, p0, p1);
        COMB2(p0, p1)
        if (lead) {
            if (grp == 0) {
                S.v1[VIX(0, h)] = p0 * zs1_[0];
                S.v1[VIX(1, h)] = p1 * zs1_[1];
            } else {
                S.gAb[VIX(0, h)] = p0;
                S.gAb[VIX(1, h)] = p1;
            }
        }
        __syncthreads();                                   // bar 3

        // flag = conv(it-2): break before this iteration's update; revert below.
        if (S.flag) { broke = 1; break; }

        // P4: A: gB = Wy0^T @ v1 -> g, rres, y1 update, residual reduce
        float qq0 = 0.f, qq1 = 0.f;
        if (grp == 0) {
            cdot(S.Wy0, S.v1, h, half, p0, p1);
            COMB2(p0, p1)
            if (lead) {
                float stepi = 4.f / (float)(it + 1);
#pragma unroll
                for (int s = 0; s < 2; s++) {
                    float gB = (s == 0) ? p0 : p1;
                    float gA = S.gAb[VIX(s, h)];
                    float g = a1r[s] * gA + a0r[s] * gB + a2w[s] + 0.5f * y1r_[s];
                    float rres = yr_[s] - g;
                    float qv = rres * rres;
                    if (s == 0) qq0 = qv; else qq1 = qv;
                    yh_[s] = y1r_[s];
                    y1r_[s] += stepi * rres;
                    S.yv0[VIX(s, h)] = y1r_[s] * a0r[s];
                    S.yv1[VIX(s, h)] = y1r_[s] * a1r[s];
                }
            }
            qq0 += __shfl_xor_sync(0xffffffffu, qq0, 1);
            qq0 += __shfl_xor_sync(0xffffffffu, qq0, 2);
            qq0 += __shfl_xor_sync(0xffffffffu, qq0, 4);
            qq0 += __shfl_xor_sync(0xffffffffu, qq0, 8);
            qq1 += __shfl_xor_sync(0xffffffffu, qq1, 1);
            qq1 += __shfl_xor_sync(0xffffffffu, qq1, 2);
            qq1 += __shfl_xor_sync(0xffffffffu, qq1, 4);
            qq1 += __shfl_xor_sync(0xffffffffu, qq1, 8);
            if (l == 0) { S.red[wh][0] = qq0; S.red[wh][1] = qq1; }
        }
        __syncthreads();                                   // bar 4
    }
    if (broke) { y1r_[0] = yh_[0]; y1r_[1] = yh_[1]; }   // revert to y1_after(it-2)

    // ---- output: mean over dims of (y1 + y) per sample ----
    float o0 = 0.f, o1 = 0.f;
    if (grp == 0 && lead) {
        o0 = y1r_[0] + yr_[0];
        o1 = y1r_[1] + yr_[1];
    }
    o0 += __shfl_xor_sync(0xffffffffu, o0, 1);
    o0 += __shfl_xor_sync(0xffffffffu, o0, 2);
    o0 += __shfl_xor_sync(0xffffffffu, o0, 4);
    o0 += __shfl_xor_sync(0xffffffffu, o0, 8);
    o1 += __shfl_xor_sync(0xffffffffu, o1, 1);
    o1 += __shfl_xor_sync(0xffffffffu, o1, 2);
    o1 += __shfl_xor_sync(0xffffffffu, o1, 4);
    o1 += __shfl_xor_sync(0xffffffffu, o1, 8);
    if (grp == 0 && l == 0) { S.red[wh][0] = o0; S.red[wh][1] = o1; }
    __syncthreads();
    if (tid == 0) {
        float t0 = 0.f, t1 = 0.f;
#pragma unroll
        for (int i = 0; i < 8; i++) { t0 += S.red[i][0]; t1 += S.red[i][1]; }
        out[samp]     = t0 * (1.f / 128.f);
        out[samp + 1] = t1 * (1.f / 128.f);
    }
}

extern "C" void kernel_launch(void* const* d_in, const int* in_sizes, int n_in,
                              void* d_out, int out_size) {
    (void)in_sizes; (void)n_in; (void)out_size;
    const float* x      = (const float*)d_in[0];
    const float* y      = (const float*)d_in[1];
    const float* wuu0_w = (const float*)d_in[2];
    const float* wuu0_b = (const float*)d_in[3];
    const float* wyu0_w = (const float*)d_in[4];
    const float* wyu0_b = (const float*)d_in[5];
    const float* wy0    = (const float*)d_in[6];
    const float* wu0_w  = (const float*)d_in[7];
    const float* wu0_b  = (const float*)d_in[8];
    const float* wuu1_w = (const float*)d_in[9];
    const float* wuu1_b = (const float*)d_in[10];
    const float* wzu1_w = (const float*)d_in[11];
    const float* wzu1_b = (const float*)d_in[12];
    const float* wz1    = (const float*)d_in[13];
    const float* wyu1_w = (const float*)d_in[14];
    const float* wyu1_b = (const float*)d_in[15];
    const float* wy1    = (const float*)d_in[16];
    const float* wu1_w  = (const float*)d_in[17];
    const float* wu1_b  = (const float*)d_in[18];
    const float* wzu2_w = (const float*)d_in[19];
    const float* wzu2_b = (const float*)d_in[20];
    const float* wz2    = (const float*)d_in[21];
    const float* wyu2_w = (const float*)d_in[22];
    const float* wyu2_b = (const float*)d_in[23];
    const float* wy2    = (const float*)d_in[24];
    // d_in[25] (wu2_w), d_in[26] (wu2_b) do not affect the gradient / output.

    size_t smem = sizeof(Smem);
    cudaFuncSetAttribute(pblnn_kernel, cudaFuncAttributeMaxDynamicSharedMemorySize, (int)smem);

    pblnn_init_kernel<<<(MAXIT * NCTA + 255) / 256, 256>>>();
    pblnn_kernel<<<NCTA, NTHREADS, smem>>>(
        x, y,
        wuu0_w, wuu0_b, wyu0_w, wyu0_b, wy0, wu0_w, wu0_b,
        wuu1_w, wuu1_b, wzu1_w, wzu1_b, wz1, wyu1_w, wyu1_b, wy1, wu1_w, wu1_b,
        wzu2_w, wzu2_b, wz2, wyu2_w, wyu2_b, wy2,
        (float*)d_out);
}